// round 15
// baseline (speedup 1.0000x reference)
#include <cuda_runtime.h>
#include <math.h>
#include <stdint.h>

// Problem constants (fixed by the dataset)
#define U_   2048
#define I_   16384
#define NN_  18432
#define F_   64
#define H_   32
#define EMAX 1000000
#define TOPK_ 3

// ---------------- device scratch (static globals; no dynamic alloc) -------
__device__ int   g_cnt_u[U_];
__device__ int   g_cnt_i[I_];
__device__ int   g_cursor[I_];
__device__ int   g_off[I_ + 1];
__device__ float g_du[U_];
__device__ float g_di[I_];
__device__ float g_Dh[U_];
__device__ float g_Pu[U_ * H_];
__device__ float g_Pi[I_ * H_];
__device__ uint2 g_csr[EMAX];          // {user, float_bits(weight)} grouped by item
__device__ float g_C[U_ * U_];         // CANONICAL upper-triangular accumulation
__device__ float g_diag[U_];           // sum of w^2 terms per user

// ---------------- kernel A0: zero the small counter arrays -----------------
__global__ void k_zero_small() {
    int idx = blockIdx.x * blockDim.x + threadIdx.x;
    int stride = gridDim.x * blockDim.x;
    for (int i = idx; i < I_; i += stride) { g_cnt_i[i] = 0; g_cursor[i] = 0; }
    for (int i = idx; i < U_; i += stride) { g_cnt_u[i] = 0; g_diag[i] = 0.0f; }
}

// ---------------- kernel B0: zero big arrays (parallel branch) -------------
// Triangular zero of C (only cells >= the row's 32-wide tile start are ever
// touched) + full zero of outS. Independent of everything until k_wpairs.
__global__ void k_zero_big(float* __restrict__ outS) {
    int idx = blockIdx.x * blockDim.x + threadIdx.x;
    int stride = gridDim.x * blockDim.x;
    float4 z = make_float4(0.f, 0.f, 0.f, 0.f);
    float4* O4 = (float4*)outS;
    const int n4 = (U_ * U_) / 4;
    for (int i = idx; i < n4; i += stride) O4[i] = z;
    int gwarp = idx >> 5, nwarps = stride >> 5, lane = idx & 31;
    for (int r = gwarp; r < U_; r += nwarps) {
        int c0 = (r >> 5) << 5;                       // 128B-aligned tile start
        float4* row4 = (float4*)(g_C + (size_t)r * U_ + c0);
        int n4r = (U_ - c0) >> 2;
        for (int j = lane; j < n4r; j += 32) row4[j] = z;
    }
}

// ---------------- kernel A1: degree histograms ------------------------------
__global__ void k_histo(const int* __restrict__ src, const int* __restrict__ dst, int E) {
    int e = blockIdx.x * blockDim.x + threadIdx.x;
    if (e < E) {
        atomicAdd(&g_cnt_u[src[e]], 1);
        atomicAdd(&g_cnt_i[dst[e]], 1);
    }
}

// ---------------- kernel A2: fused scan + log1p degrees (1 block) ----------
__global__ void k_scan_findeg(float* __restrict__ out_du, int write_du) {
    __shared__ int wsum[32];
    int t = threadIdx.x;
    int lane = t & 31, wid = t >> 5;
    const int PER = I_ / 1024;           // 16
    int base = t * PER;
    int loc[PER];
    int s = 0;
    #pragma unroll
    for (int j = 0; j < PER; j++) {
        int c = g_cnt_i[base + j];
        loc[j] = s;
        s += c;
        g_di[base + j] = log1pf((float)c);
    }
    int v = s;
    #pragma unroll
    for (int off = 1; off < 32; off <<= 1) {
        int u = __shfl_up_sync(0xffffffffu, v, off);
        if (lane >= off) v += u;
    }
    if (lane == 31) wsum[wid] = v;
    __syncthreads();
    if (wid == 0) {
        int wv = wsum[lane];
        #pragma unroll
        for (int off = 1; off < 32; off <<= 1) {
            int u = __shfl_up_sync(0xffffffffu, wv, off);
            if (lane >= off) wv += u;
        }
        wsum[lane] = wv;
    }
    __syncthreads();
    int prefix = (v - s) + (wid ? wsum[wid - 1] : 0);
    #pragma unroll
    for (int j = 0; j < PER; j++) g_off[base + j] = prefix + loc[j];
    if (t == 1023) g_off[I_] = prefix + s;

    for (int i = t; i < U_; i += 1024) {
        float du = log1pf((float)g_cnt_u[i]);
        g_du[i] = du;
        g_Dh[i] = sqrtf(du);
        if (write_du) out_du[i] = du;
    }
}

// ---------------- kernel A3: per-node projections (R10 measured best) ------
__global__ void k_proj(const float* __restrict__ x, const float* __restrict__ w1,
                       const float* __restrict__ b1) {
    __shared__ float swu[65 * 32];   // user cols [f][h]: f 0..63 + degree col
    __shared__ float swi[65 * 32];   // item cols
    __shared__ float sb1[32];
    __shared__ float sx[32][64];
    for (int i = threadIdx.x; i < 65 * 32; i += 256) {
        int f = i >> 5, h = i & 31;
        swu[i] = w1[h * 130 + f];
        swi[i] = w1[h * 130 + 65 + f];
    }
    if (threadIdx.x < 32) sb1[threadIdx.x] = b1[threadIdx.x];
    int nb0 = blockIdx.x * 32;
    for (int i = threadIdx.x; i < 32 * 64; i += 256) {
        int node = nb0 + (i >> 6);
        sx[i >> 6][i & 63] = x[(size_t)node * F_ + (i & 63)];
    }
    __syncthreads();
    int warp = threadIdx.x >> 5, lane = threadIdx.x & 31;
    int n0 = nb0 + warp * 4;                 // never straddles the U_ boundary
    bool is_user = (n0 < U_);
    const float* W = is_user ? swu : swi;
    const float* x0 = sx[warp * 4 + 0];
    const float* x1 = sx[warp * 4 + 1];
    const float* x2 = sx[warp * 4 + 2];
    const float* x3 = sx[warp * 4 + 3];
    float a0 = 0.f, a1 = 0.f, a2 = 0.f, a3 = 0.f;
    #pragma unroll
    for (int f = 0; f < F_; f++) {
        float w = W[f * 32 + lane];
        a0 = fmaf(x0[f], w, a0);
        a1 = fmaf(x1[f], w, a1);
        a2 = fmaf(x2[f], w, a2);
        a3 = fmaf(x3[f], w, a3);
    }
    float wd = W[64 * 32 + lane];
    if (is_user) {
        float b = sb1[lane];
        g_Pu[(n0 + 0) * H_ + lane] = a0 + g_du[n0 + 0] * wd + b;
        g_Pu[(n0 + 1) * H_ + lane] = a1 + g_du[n0 + 1] * wd + b;
        g_Pu[(n0 + 2) * H_ + lane] = a2 + g_du[n0 + 2] * wd + b;
        g_Pu[(n0 + 3) * H_ + lane] = a3 + g_du[n0 + 3] * wd + b;
    } else {
        int i0 = n0 - U_;
        g_Pi[(i0 + 0) * H_ + lane] = a0 + g_di[i0 + 0] * wd;
        g_Pi[(i0 + 1) * H_ + lane] = a1 + g_di[i0 + 1] * wd;
        g_Pi[(i0 + 2) * H_ + lane] = a2 + g_di[i0 + 2] * wd;
        g_Pi[(i0 + 3) * H_ + lane] = a3 + g_di[i0 + 3] * wd;
    }
}

// ---------------- kernel A4: CSR position scatter (user ids only) ----------
__global__ void k_scatter(const int* __restrict__ src, const int* __restrict__ dst, int E) {
    int e = blockIdx.x * blockDim.x + threadIdx.x;
    if (e >= E) return;
    int it = dst[e];
    int pos = g_off[it] + atomicAdd(&g_cursor[it], 1);
    if (pos < EMAX) g_csr[pos].x = (unsigned)src[e];
}

// ---------------- kernel 5: FUSED weights + pair products (R13 winner) -----
__global__ void k_wpairs(const float* __restrict__ w2, const float* __restrict__ b2) {
    __shared__ float sPi[H_];
    __shared__ float sw2[H_];
    int item = blockIdx.x;
    int base = g_off[item];
    int k = g_off[item + 1] - base;
    if (k <= 0) return;
    int t = threadIdx.x;
    if (t < H_) {
        sPi[t] = g_Pi[item * H_ + t];
        sw2[t] = w2[t];
    }
    __syncthreads();
    float b2v = b2[0];
    for (int i = t; i < k; i += 256) {
        unsigned u = g_csr[base + i].x;
        const float4* pu = (const float4*)(g_Pu + (size_t)u * H_);
        float s = 0.0f;
        #pragma unroll
        for (int j = 0; j < H_ / 4; j++) {
            float4 a = pu[j];
            s = fmaf(fmaxf(a.x + sPi[4 * j + 0], 0.0f), sw2[4 * j + 0], s);
            s = fmaf(fmaxf(a.y + sPi[4 * j + 1], 0.0f), sw2[4 * j + 1], s);
            s = fmaf(fmaxf(a.z + sPi[4 * j + 2], 0.0f), sw2[4 * j + 2], s);
            s = fmaf(fmaxf(a.w + sPi[4 * j + 3], 0.0f), sw2[4 * j + 3], s);
        }
        float w = 1.0f / (1.0f + expf(-(s + b2v)));
        atomicAdd(&g_diag[u], w * w);
        g_csr[base + i] = make_uint2(u, __float_as_uint(w));   // single ST.64
    }
    __syncthreads();
    if (k <= 1) return;
    int warp = t >> 5;
    int lane = t & 31;
    for (int a = warp; a < k; a += 8) {
        uint2 ea = g_csr[base + a];              // L1-hot broadcast load
        float wa = __uint_as_float(ea.y);
        unsigned ua = ea.x;
        for (int b = a + 1 + lane; b < k; b += 32) {
            uint2 eb = g_csr[base + b];          // L1-hot
            unsigned ub = eb.x;
            unsigned lo = min(ua, ub), hi = max(ua, ub);
            atomicAdd(&g_C[(lo << 11) + hi], wa * __uint_as_float(eb.y));
        }
    }
}

// ---------------- kernel 6: sym + scale + top-3 + scatter S (R8 winner) ----
__device__ __forceinline__ bool better(float v, int i, float bv, int bi) {
    return (v > bv) || (v == bv && (unsigned)i < (unsigned)bi);
}
__device__ __forceinline__ void ins3(float v, int i,
                                     float& v0, int& i0, float& v1, int& i1,
                                     float& v2, int& i2) {
    if (better(v, i, v0, i0)) { v2 = v1; i2 = i1; v1 = v0; i1 = i0; v0 = v; i0 = i; }
    else if (better(v, i, v1, i1)) { v2 = v1; i2 = i1; v1 = v; i1 = i; }
    else if (better(v, i, v2, i2)) { v2 = v; i2 = i; }
}

__global__ void k_topk(float* __restrict__ outS) {
    __shared__ float sDh[U_];            // 8 KB
    __shared__ float sB[32][9];          // transposed tile: sB[c_local][r_local]
    int tx = threadIdx.x, ty = threadIdx.y;     // (32,8)
    int tid = ty * 32 + tx;
    for (int i = tid; i < U_; i += 256) sDh[i] = g_Dh[i];
    __syncthreads();
    int r0 = blockIdx.x * 8;
    int d0 = (r0 >> 5) << 5;             // the 32-wide tile containing rows r0..r0+7
    int r = r0 + ty;
    float dhr = sDh[r];
    float dg = g_diag[r];
    float v0 = -1.0f, v1 = -1.0f, v2 = -1.0f;
    int   i0 = -1,    i1 = -1,    i2 = -1;
    int li = tid >> 3, lj = tid & 7;     // load coords for transposed tile
    for (int c0 = 0; c0 < U_; c0 += 32) {
        bool useT = (c0 <= d0);          // uniform across block
        bool useD = (c0 >= d0);
        if (useT) {
            __syncthreads();             // protect sB reuse across iterations
            sB[li][lj] = g_C[(size_t)(c0 + li) * U_ + (r0 + lj)];
            __syncthreads();
        }
        int c = c0 + tx;
        float val = 0.0f;
        if (useD) val += g_C[(size_t)r * U_ + c];   // upper triangle / diagonal
        if (useT) val += sB[tx][ty];                // C[c][r] (upper triangle)
        if (c == r) val += dg;
        float v = val * dhr * sDh[c];
        if (v > 0.0f) ins3(v, c, v0, i0, v1, i1, v2, i2);
    }
    #pragma unroll
    for (int off = 16; off > 0; off >>= 1) {
        float ov0 = __shfl_down_sync(0xffffffffu, v0, off);
        float ov1 = __shfl_down_sync(0xffffffffu, v1, off);
        float ov2 = __shfl_down_sync(0xffffffffu, v2, off);
        int   oi0 = __shfl_down_sync(0xffffffffu, i0, off);
        int   oi1 = __shfl_down_sync(0xffffffffu, i1, off);
        int   oi2 = __shfl_down_sync(0xffffffffu, i2, off);
        if (ov0 > 0.0f) ins3(ov0, oi0, v0, i0, v1, i1, v2, i2);
        if (ov1 > 0.0f) ins3(ov1, oi1, v0, i0, v1, i1, v2, i2);
        if (ov2 > 0.0f) ins3(ov2, oi2, v0, i0, v1, i1, v2, i2);
    }
    if (tx == 0) {
        float mv[3] = {v0, v1, v2};
        int   mi[3] = {i0, i1, i2};
        #pragma unroll
        for (int q = 0; q < 3; q++) {
            if (mv[q] > 0.0f) {
                float vh = 0.5f * mv[q];
                atomicAdd(&outS[(size_t)r * U_ + mi[q]], vh);
                atomicAdd(&outS[(size_t)mi[q] * U_ + r], vh);
            }
        }
    }
}

// ---------------------------------------------------------------------------
// Fork/join across two streams so the graph gets parallel branches:
//   branch B (s2): zero_big(C, outS)            -> proj (after scan event)
//   branch A (0):  zero_small -> histo -> scan  -> scatter
//   join: wpairs waits on branch B (covers zero_big + proj), then topk.
// Streams/events are created and destroyed every call (deterministic; no
// device memory allocation). Capture turns record/wait into graph edges.
extern "C" void kernel_launch(void* const* d_in, const int* in_sizes, int n_in,
                              void* d_out, int out_size) {
    const float* x   = (const float*)d_in[0];
    const float* w1  = (const float*)d_in[1];
    const float* b1  = (const float*)d_in[2];
    const float* w2  = (const float*)d_in[3];
    const float* b2  = (const float*)d_in[4];
    const int*   src = (const int*)d_in[5];
    const int*   dst = (const int*)d_in[6];
    int E = in_sizes[5];
    if (E > EMAX) E = EMAX;

    float* outS = (float*)d_out;
    int write_du = (out_size >= U_ * U_ + U_) ? 1 : 0;

    cudaStream_t s2;
    cudaEvent_t evFork, evScan, evB;
    bool forked =
        (cudaStreamCreateWithFlags(&s2, cudaStreamNonBlocking) == cudaSuccess) &&
        (cudaEventCreateWithFlags(&evFork, cudaEventDisableTiming) == cudaSuccess) &&
        (cudaEventCreateWithFlags(&evScan, cudaEventDisableTiming) == cudaSuccess) &&
        (cudaEventCreateWithFlags(&evB,    cudaEventDisableTiming) == cudaSuccess);

    if (forked) {
        // fork point: branch B may start immediately
        cudaEventRecord(evFork, 0);
        cudaStreamWaitEvent(s2, evFork, 0);
        k_zero_big<<<1024, 256, 0, s2>>>(outS);

        // branch A
        k_zero_small<<<64, 256>>>();
        k_histo<<<(E + 255) / 256, 256>>>(src, dst, E);
        k_scan_findeg<<<1, 1024>>>(outS + (size_t)U_ * U_, write_du);
        cudaEventRecord(evScan, 0);

        // branch B continues: proj depends on scan
        cudaStreamWaitEvent(s2, evScan, 0);
        k_proj<<<NN_ / 32, 256, 0, s2>>>(x, w1, b1);
        cudaEventRecord(evB, s2);

        // branch A continues in parallel with proj
        k_scatter<<<(E + 255) / 256, 256>>>(src, dst, E);

        // join, then the hot chain
        cudaStreamWaitEvent(0, evB, 0);
        k_wpairs<<<I_, 256>>>(w2, b2);
        k_topk<<<U_ / 8, dim3(32, 8)>>>(outS);

        cudaEventDestroy(evFork);
        cudaEventDestroy(evScan);
        cudaEventDestroy(evB);
        cudaStreamDestroy(s2);
    } else {
        // serial fallback (identical work, R13/R14 ordering)
        k_zero_small<<<64, 256>>>();
        k_zero_big<<<1024, 256>>>(outS);
        k_histo<<<(E + 255) / 256, 256>>>(src, dst, E);
        k_scan_findeg<<<1, 1024>>>(outS + (size_t)U_ * U_, write_du);
        k_proj<<<NN_ / 32, 256>>>(x, w1, b1);
        k_scatter<<<(E + 255) / 256, 256>>>(src, dst, E);
        k_wpairs<<<I_, 256>>>(w2, b2);
        k_topk<<<U_ / 8, dim3(32, 8)>>>(outS);
    }
}

// round 16
// speedup vs baseline: 1.0269x; 1.0269x over previous
#include <cuda_runtime.h>
#include <math.h>
#include <stdint.h>

// Problem constants (fixed by the dataset)
#define U_   2048
#define I_   16384
#define NN_  18432
#define F_   64
#define H_   32
#define EMAX 1000000
#define TOPK_ 3

// ---------------- device scratch (static globals; no dynamic alloc) -------
__device__ int   g_cnt_u[U_];
__device__ int   g_cnt_i[I_];
__device__ int   g_cursor[I_];
__device__ int   g_off[I_ + 1];
__device__ float g_du[U_];
__device__ float g_di[I_];
__device__ float g_Dh[U_];
__device__ float g_Pu[U_ * H_];
__device__ float g_Pi[I_ * H_];
__device__ uint2 g_csr[EMAX];          // {user, float_bits(weight)} grouped by item
__device__ float g_C[U_ * U_];         // CANONICAL upper-triangular accumulation
__device__ float g_diag[U_];           // sum of w^2 terms per user

// ---------------- kernel 0: zero the small counter arrays ------------------
__global__ void k_zero_small() {
    int idx = blockIdx.x * blockDim.x + threadIdx.x;
    int stride = gridDim.x * blockDim.x;
    for (int i = idx; i < I_; i += stride) { g_cnt_i[i] = 0; g_cursor[i] = 0; }
    for (int i = idx; i < U_; i += stride) { g_cnt_u[i] = 0; g_diag[i] = 0.0f; }
}

// ---------------- kernel 1: zero big arrays + degree histograms (fused) ----
__global__ void k_init(float* __restrict__ outS,
                       const int* __restrict__ src, const int* __restrict__ dst, int E) {
    int idx = blockIdx.x * blockDim.x + threadIdx.x;
    int stride = gridDim.x * blockDim.x;
    for (int e = idx; e < E; e += stride) {
        atomicAdd(&g_cnt_u[src[e]], 1);
        atomicAdd(&g_cnt_i[dst[e]], 1);
    }
    float4 z = make_float4(0.f, 0.f, 0.f, 0.f);
    float4* O4 = (float4*)outS;
    const int n4 = (U_ * U_) / 4;
    for (int i = idx; i < n4; i += stride) O4[i] = z;
    // triangular zero of C: one warp per row, float4 stores from tile start
    int gwarp = idx >> 5, nwarps = stride >> 5, lane = idx & 31;
    for (int r = gwarp; r < U_; r += nwarps) {
        int c0 = (r >> 5) << 5;                       // 128B-aligned tile start
        float4* row4 = (float4*)(g_C + (size_t)r * U_ + c0);
        int n4r = (U_ - c0) >> 2;
        for (int j = lane; j < n4r; j += 32) row4[j] = z;
    }
}

// ---------------- kernel 2a: wide log1p/sqrt of degrees (64 blocks) --------
// MUFU work spread across the chip instead of serialized on one SM.
__global__ void k_findeg(float* __restrict__ out_du, int write_du) {
    int idx = blockIdx.x * blockDim.x + threadIdx.x;
    if (idx < I_) g_di[idx] = log1pf((float)g_cnt_i[idx]);
    if (idx < U_) {
        float du = log1pf((float)g_cnt_u[idx]);
        g_du[idx] = du;
        g_Dh[idx] = sqrtf(du);
        if (write_du) out_du[idx] = du;
    }
}

// ---------------- kernel 2b: integer-only exclusive scan (1 block) ---------
__global__ void k_scan() {
    __shared__ int wsum[32];
    int t = threadIdx.x;
    int lane = t & 31, wid = t >> 5;
    const int PER = I_ / 1024;           // 16
    int base = t * PER;
    int loc[PER];
    int s = 0;
    #pragma unroll
    for (int j = 0; j < PER; j++) {
        int c = g_cnt_i[base + j];
        loc[j] = s;
        s += c;
    }
    int v = s;
    #pragma unroll
    for (int off = 1; off < 32; off <<= 1) {
        int u = __shfl_up_sync(0xffffffffu, v, off);
        if (lane >= off) v += u;
    }
    if (lane == 31) wsum[wid] = v;
    __syncthreads();
    if (wid == 0) {
        int wv = wsum[lane];
        #pragma unroll
        for (int off = 1; off < 32; off <<= 1) {
            int u = __shfl_up_sync(0xffffffffu, wv, off);
            if (lane >= off) wv += u;
        }
        wsum[lane] = wv;
    }
    __syncthreads();
    int prefix = (v - s) + (wid ? wsum[wid - 1] : 0);
    #pragma unroll
    for (int j = 0; j < PER; j++) g_off[base + j] = prefix + loc[j];
    if (t == 1023) g_off[I_] = prefix + s;
}

// ---------------- kernel 3: per-node projections (R10 measured best) -------
__global__ void k_proj(const float* __restrict__ x, const float* __restrict__ w1,
                       const float* __restrict__ b1) {
    __shared__ float swu[65 * 32];   // user cols [f][h]: f 0..63 + degree col
    __shared__ float swi[65 * 32];   // item cols
    __shared__ float sb1[32];
    __shared__ float sx[32][64];
    for (int i = threadIdx.x; i < 65 * 32; i += 256) {
        int f = i >> 5, h = i & 31;
        swu[i] = w1[h * 130 + f];
        swi[i] = w1[h * 130 + 65 + f];
    }
    if (threadIdx.x < 32) sb1[threadIdx.x] = b1[threadIdx.x];
    int nb0 = blockIdx.x * 32;
    for (int i = threadIdx.x; i < 32 * 64; i += 256) {
        int node = nb0 + (i >> 6);
        sx[i >> 6][i & 63] = x[(size_t)node * F_ + (i & 63)];
    }
    __syncthreads();
    int warp = threadIdx.x >> 5, lane = threadIdx.x & 31;
    int n0 = nb0 + warp * 4;                 // never straddles the U_ boundary
    bool is_user = (n0 < U_);
    const float* W = is_user ? swu : swi;
    const float* x0 = sx[warp * 4 + 0];
    const float* x1 = sx[warp * 4 + 1];
    const float* x2 = sx[warp * 4 + 2];
    const float* x3 = sx[warp * 4 + 3];
    float a0 = 0.f, a1 = 0.f, a2 = 0.f, a3 = 0.f;
    #pragma unroll
    for (int f = 0; f < F_; f++) {
        float w = W[f * 32 + lane];
        a0 = fmaf(x0[f], w, a0);
        a1 = fmaf(x1[f], w, a1);
        a2 = fmaf(x2[f], w, a2);
        a3 = fmaf(x3[f], w, a3);
    }
    float wd = W[64 * 32 + lane];
    if (is_user) {
        float b = sb1[lane];
        g_Pu[(n0 + 0) * H_ + lane] = a0 + g_du[n0 + 0] * wd + b;
        g_Pu[(n0 + 1) * H_ + lane] = a1 + g_du[n0 + 1] * wd + b;
        g_Pu[(n0 + 2) * H_ + lane] = a2 + g_du[n0 + 2] * wd + b;
        g_Pu[(n0 + 3) * H_ + lane] = a3 + g_du[n0 + 3] * wd + b;
    } else {
        int i0 = n0 - U_;
        g_Pi[(i0 + 0) * H_ + lane] = a0 + g_di[i0 + 0] * wd;
        g_Pi[(i0 + 1) * H_ + lane] = a1 + g_di[i0 + 1] * wd;
        g_Pi[(i0 + 2) * H_ + lane] = a2 + g_di[i0 + 2] * wd;
        g_Pi[(i0 + 3) * H_ + lane] = a3 + g_di[i0 + 3] * wd;
    }
}

// ---------------- kernel 4: CSR position scatter (user ids only) -----------
__global__ void k_scatter(const int* __restrict__ src, const int* __restrict__ dst, int E) {
    int e = blockIdx.x * blockDim.x + threadIdx.x;
    if (e >= E) return;
    int it = dst[e];
    int pos = g_off[it] + atomicAdd(&g_cursor[it], 1);
    if (pos < EMAX) g_csr[pos].x = (unsigned)src[e];
}

// ---------------- kernel 5: FUSED weights + pair products (R13 winner) -----
__global__ void k_wpairs(const float* __restrict__ w2, const float* __restrict__ b2) {
    __shared__ float sPi[H_];
    __shared__ float sw2[H_];
    int item = blockIdx.x;
    int base = g_off[item];
    int k = g_off[item + 1] - base;
    if (k <= 0) return;
    int t = threadIdx.x;
    if (t < H_) {
        sPi[t] = g_Pi[item * H_ + t];
        sw2[t] = w2[t];
    }
    __syncthreads();
    float b2v = b2[0];
    for (int i = t; i < k; i += 256) {
        unsigned u = g_csr[base + i].x;
        const float4* pu = (const float4*)(g_Pu + (size_t)u * H_);
        float s = 0.0f;
        #pragma unroll
        for (int j = 0; j < H_ / 4; j++) {
            float4 a = pu[j];
            s = fmaf(fmaxf(a.x + sPi[4 * j + 0], 0.0f), sw2[4 * j + 0], s);
            s = fmaf(fmaxf(a.y + sPi[4 * j + 1], 0.0f), sw2[4 * j + 1], s);
            s = fmaf(fmaxf(a.z + sPi[4 * j + 2], 0.0f), sw2[4 * j + 2], s);
            s = fmaf(fmaxf(a.w + sPi[4 * j + 3], 0.0f), sw2[4 * j + 3], s);
        }
        float w = 1.0f / (1.0f + expf(-(s + b2v)));
        atomicAdd(&g_diag[u], w * w);
        g_csr[base + i] = make_uint2(u, __float_as_uint(w));   // single ST.64
    }
    __syncthreads();
    if (k <= 1) return;
    int warp = t >> 5;
    int lane = t & 31;
    for (int a = warp; a < k; a += 8) {
        uint2 ea = g_csr[base + a];              // L1-hot broadcast load
        float wa = __uint_as_float(ea.y);
        unsigned ua = ea.x;
        for (int b = a + 1 + lane; b < k; b += 32) {
            uint2 eb = g_csr[base + b];          // L1-hot
            unsigned ub = eb.x;
            unsigned lo = min(ua, ub), hi = max(ua, ub);
            atomicAdd(&g_C[(lo << 11) + hi], wa * __uint_as_float(eb.y));
        }
    }
}

// ---------------- kernel 6: sym + scale + top-3 + scatter S (R8 winner) ----
__device__ __forceinline__ bool better(float v, int i, float bv, int bi) {
    return (v > bv) || (v == bv && (unsigned)i < (unsigned)bi);
}
__device__ __forceinline__ void ins3(float v, int i,
                                     float& v0, int& i0, float& v1, int& i1,
                                     float& v2, int& i2) {
    if (better(v, i, v0, i0)) { v2 = v1; i2 = i1; v1 = v0; i1 = i0; v0 = v; i0 = i; }
    else if (better(v, i, v1, i1)) { v2 = v1; i2 = i1; v1 = v; i1 = i; }
    else if (better(v, i, v2, i2)) { v2 = v; i2 = i; }
}

__global__ void k_topk(float* __restrict__ outS) {
    __shared__ float sDh[U_];            // 8 KB
    __shared__ float sB[32][9];          // transposed tile: sB[c_local][r_local]
    int tx = threadIdx.x, ty = threadIdx.y;     // (32,8)
    int tid = ty * 32 + tx;
    for (int i = tid; i < U_; i += 256) sDh[i] = g_Dh[i];
    __syncthreads();
    int r0 = blockIdx.x * 8;
    int d0 = (r0 >> 5) << 5;             // the 32-wide tile containing rows r0..r0+7
    int r = r0 + ty;
    float dhr = sDh[r];
    float dg = g_diag[r];
    float v0 = -1.0f, v1 = -1.0f, v2 = -1.0f;
    int   i0 = -1,    i1 = -1,    i2 = -1;
    int li = tid >> 3, lj = tid & 7;     // load coords for transposed tile
    for (int c0 = 0; c0 < U_; c0 += 32) {
        bool useT = (c0 <= d0);          // uniform across block
        bool useD = (c0 >= d0);
        if (useT) {
            __syncthreads();             // protect sB reuse across iterations
            sB[li][lj] = g_C[(size_t)(c0 + li) * U_ + (r0 + lj)];
            __syncthreads();
        }
        int c = c0 + tx;
        float val = 0.0f;
        if (useD) val += g_C[(size_t)r * U_ + c];   // upper triangle / diagonal
        if (useT) val += sB[tx][ty];                // C[c][r] (upper triangle)
        if (c == r) val += dg;
        float v = val * dhr * sDh[c];
        if (v > 0.0f) ins3(v, c, v0, i0, v1, i1, v2, i2);
    }
    #pragma unroll
    for (int off = 16; off > 0; off >>= 1) {
        float ov0 = __shfl_down_sync(0xffffffffu, v0, off);
        float ov1 = __shfl_down_sync(0xffffffffu, v1, off);
        float ov2 = __shfl_down_sync(0xffffffffu, v2, off);
        int   oi0 = __shfl_down_sync(0xffffffffu, i0, off);
        int   oi1 = __shfl_down_sync(0xffffffffu, i1, off);
        int   oi2 = __shfl_down_sync(0xffffffffu, i2, off);
        if (ov0 > 0.0f) ins3(ov0, oi0, v0, i0, v1, i1, v2, i2);
        if (ov1 > 0.0f) ins3(ov1, oi1, v0, i0, v1, i1, v2, i2);
        if (ov2 > 0.0f) ins3(ov2, oi2, v0, i0, v1, i1, v2, i2);
    }
    if (tx == 0) {
        float mv[3] = {v0, v1, v2};
        int   mi[3] = {i0, i1, i2};
        #pragma unroll
        for (int q = 0; q < 3; q++) {
            if (mv[q] > 0.0f) {
                float vh = 0.5f * mv[q];
                atomicAdd(&outS[(size_t)r * U_ + mi[q]], vh);
                atomicAdd(&outS[(size_t)mi[q] * U_ + r], vh);
            }
        }
    }
}

// ---------------------------------------------------------------------------
extern "C" void kernel_launch(void* const* d_in, const int* in_sizes, int n_in,
                              void* d_out, int out_size) {
    const float* x   = (const float*)d_in[0];
    const float* w1  = (const float*)d_in[1];
    const float* b1  = (const float*)d_in[2];
    const float* w2  = (const float*)d_in[3];
    const float* b2  = (const float*)d_in[4];
    const int*   src = (const int*)d_in[5];
    const int*   dst = (const int*)d_in[6];
    int E = in_sizes[5];
    if (E > EMAX) E = EMAX;

    float* outS = (float*)d_out;
    int write_du = (out_size >= U_ * U_ + U_) ? 1 : 0;

    k_zero_small<<<64, 256>>>();
    k_init<<<1024, 256>>>(outS, src, dst, E);
    k_findeg<<<(I_ + 255) / 256, 256>>>(outS + (size_t)U_ * U_, write_du);
    k_scan<<<1, 1024>>>();
    k_proj<<<NN_ / 32, 256>>>(x, w1, b1);
    k_scatter<<<(E + 255) / 256, 256>>>(src, dst, E);
    k_wpairs<<<I_, 256>>>(w2, b2);
    k_topk<<<U_ / 8, dim3(32, 8)>>>(outS);
}

// round 17
// speedup vs baseline: 1.0748x; 1.0466x over previous
#include <cuda_runtime.h>
#include <math.h>
#include <stdint.h>

// Problem constants (fixed by the dataset)
#define U_   2048
#define I_   16384
#define NN_  18432
#define F_   64
#define H_   32
#define EMAX 1000000
#define TOPK_ 3

// ---------------- device scratch (static globals; no dynamic alloc) -------
__device__ int   g_cnt_u[U_];
__device__ int   g_cnt_i[I_];
__device__ int   g_cursor[I_];
__device__ int   g_off[I_];            // per-item base (disjoint ranges, NOT a prefix sum)
__device__ int   g_alloc;              // global allocation cursor
__device__ float g_du[U_];
__device__ float g_di[I_];
__device__ float g_Dh[U_];
__device__ float g_Pu[U_ * H_];
__device__ float g_Pi[I_ * H_];
__device__ uint2 g_csr[EMAX];          // {user, float_bits(weight)} grouped by item
__device__ float g_C[U_ * U_];         // CANONICAL upper-triangular accumulation
__device__ float g_diag[U_];           // sum of w^2 terms per user

// ---------------- kernel 0: zero the small counter arrays ------------------
__global__ void k_zero_small() {
    int idx = blockIdx.x * blockDim.x + threadIdx.x;
    int stride = gridDim.x * blockDim.x;
    for (int i = idx; i < I_; i += stride) { g_cnt_i[i] = 0; g_cursor[i] = 0; }
    for (int i = idx; i < U_; i += stride) { g_cnt_u[i] = 0; g_diag[i] = 0.0f; }
    if (idx == 0) g_alloc = 0;
}

// ---------------- kernel 1: zero big arrays + degree histograms (fused) ----
__global__ void k_init(float* __restrict__ outS,
                       const int* __restrict__ src, const int* __restrict__ dst, int E) {
    int idx = blockIdx.x * blockDim.x + threadIdx.x;
    int stride = gridDim.x * blockDim.x;
    for (int e = idx; e < E; e += stride) {
        atomicAdd(&g_cnt_u[src[e]], 1);
        atomicAdd(&g_cnt_i[dst[e]], 1);
    }
    float4 z = make_float4(0.f, 0.f, 0.f, 0.f);
    float4* O4 = (float4*)outS;
    const int n4 = (U_ * U_) / 4;
    for (int i = idx; i < n4; i += stride) O4[i] = z;
    // triangular zero of C: one warp per row, float4 stores from tile start
    int gwarp = idx >> 5, nwarps = stride >> 5, lane = idx & 31;
    for (int r = gwarp; r < U_; r += nwarps) {
        int c0 = (r >> 5) << 5;                       // 128B-aligned tile start
        float4* row4 = (float4*)(g_C + (size_t)r * U_ + c0);
        int n4r = (U_ - c0) >> 2;
        for (int j = lane; j < n4r; j += 32) row4[j] = z;
    }
}

// ---------------- kernel 2: wide degree finalize + CSR base allocation -----
// 64 blocks. log1p/sqrt spread across the chip, and per-item CSR bases via
// warp-aggregated atomicAdd on one cursor (512 atomics total). No prefix-sum
// kernel, no single-block launch: g_off[i] is just a disjoint base; wpairs
// reads the count from g_cnt_i directly.
__global__ void k_findeg(float* __restrict__ out_du, int write_du) {
    int idx = blockIdx.x * blockDim.x + threadIdx.x;   // exactly [0, I_)
    int lane = idx & 31;
    int cnt = g_cnt_i[idx];
    g_di[idx] = log1pf((float)cnt);
    // warp inclusive scan of counts
    int v = cnt;
    #pragma unroll
    for (int off = 1; off < 32; off <<= 1) {
        int u = __shfl_up_sync(0xffffffffu, v, off);
        if (lane >= off) v += u;
    }
    int base = 0;
    if (lane == 31) base = atomicAdd(&g_alloc, v);     // v = warp total
    base = __shfl_sync(0xffffffffu, base, 31);
    g_off[idx] = base + (v - cnt);                     // exclusive within warp
    if (idx < U_) {
        float du = log1pf((float)g_cnt_u[idx]);
        g_du[idx] = du;
        g_Dh[idx] = sqrtf(du);
        if (write_du) out_du[idx] = du;
    }
}

// ---------------- kernel 3: per-node projections (R10 measured best) -------
__global__ void k_proj(const float* __restrict__ x, const float* __restrict__ w1,
                       const float* __restrict__ b1) {
    __shared__ float swu[65 * 32];   // user cols [f][h]: f 0..63 + degree col
    __shared__ float swi[65 * 32];   // item cols
    __shared__ float sb1[32];
    __shared__ float sx[32][64];
    for (int i = threadIdx.x; i < 65 * 32; i += 256) {
        int f = i >> 5, h = i & 31;
        swu[i] = w1[h * 130 + f];
        swi[i] = w1[h * 130 + 65 + f];
    }
    if (threadIdx.x < 32) sb1[threadIdx.x] = b1[threadIdx.x];
    int nb0 = blockIdx.x * 32;
    for (int i = threadIdx.x; i < 32 * 64; i += 256) {
        int node = nb0 + (i >> 6);
        sx[i >> 6][i & 63] = x[(size_t)node * F_ + (i & 63)];
    }
    __syncthreads();
    int warp = threadIdx.x >> 5, lane = threadIdx.x & 31;
    int n0 = nb0 + warp * 4;                 // never straddles the U_ boundary
    bool is_user = (n0 < U_);
    const float* W = is_user ? swu : swi;
    const float* x0 = sx[warp * 4 + 0];
    const float* x1 = sx[warp * 4 + 1];
    const float* x2 = sx[warp * 4 + 2];
    const float* x3 = sx[warp * 4 + 3];
    float a0 = 0.f, a1 = 0.f, a2 = 0.f, a3 = 0.f;
    #pragma unroll
    for (int f = 0; f < F_; f++) {
        float w = W[f * 32 + lane];
        a0 = fmaf(x0[f], w, a0);
        a1 = fmaf(x1[f], w, a1);
        a2 = fmaf(x2[f], w, a2);
        a3 = fmaf(x3[f], w, a3);
    }
    float wd = W[64 * 32 + lane];
    if (is_user) {
        float b = sb1[lane];
        g_Pu[(n0 + 0) * H_ + lane] = a0 + g_du[n0 + 0] * wd + b;
        g_Pu[(n0 + 1) * H_ + lane] = a1 + g_du[n0 + 1] * wd + b;
        g_Pu[(n0 + 2) * H_ + lane] = a2 + g_du[n0 + 2] * wd + b;
        g_Pu[(n0 + 3) * H_ + lane] = a3 + g_du[n0 + 3] * wd + b;
    } else {
        int i0 = n0 - U_;
        g_Pi[(i0 + 0) * H_ + lane] = a0 + g_di[i0 + 0] * wd;
        g_Pi[(i0 + 1) * H_ + lane] = a1 + g_di[i0 + 1] * wd;
        g_Pi[(i0 + 2) * H_ + lane] = a2 + g_di[i0 + 2] * wd;
        g_Pi[(i0 + 3) * H_ + lane] = a3 + g_di[i0 + 3] * wd;
    }
}

// ---------------- kernel 4: CSR position scatter (user ids only) -----------
__global__ void k_scatter(const int* __restrict__ src, const int* __restrict__ dst, int E) {
    int e = blockIdx.x * blockDim.x + threadIdx.x;
    if (e >= E) return;
    int it = dst[e];
    int pos = g_off[it] + atomicAdd(&g_cursor[it], 1);
    if (pos < EMAX) g_csr[pos].x = (unsigned)src[e];
}

// ---------------- kernel 5: FUSED weights + pair products (R13 winner) -----
// k comes from g_cnt_i (g_off is a base, not a prefix sum).
__global__ void k_wpairs(const float* __restrict__ w2, const float* __restrict__ b2) {
    __shared__ float sPi[H_];
    __shared__ float sw2[H_];
    int item = blockIdx.x;
    int base = g_off[item];
    int k = g_cnt_i[item];
    if (k <= 0) return;
    int t = threadIdx.x;
    if (t < H_) {
        sPi[t] = g_Pi[item * H_ + t];
        sw2[t] = w2[t];
    }
    __syncthreads();
    float b2v = b2[0];
    for (int i = t; i < k; i += 256) {
        unsigned u = g_csr[base + i].x;
        const float4* pu = (const float4*)(g_Pu + (size_t)u * H_);
        float s = 0.0f;
        #pragma unroll
        for (int j = 0; j < H_ / 4; j++) {
            float4 a = pu[j];
            s = fmaf(fmaxf(a.x + sPi[4 * j + 0], 0.0f), sw2[4 * j + 0], s);
            s = fmaf(fmaxf(a.y + sPi[4 * j + 1], 0.0f), sw2[4 * j + 1], s);
            s = fmaf(fmaxf(a.z + sPi[4 * j + 2], 0.0f), sw2[4 * j + 2], s);
            s = fmaf(fmaxf(a.w + sPi[4 * j + 3], 0.0f), sw2[4 * j + 3], s);
        }
        float w = 1.0f / (1.0f + expf(-(s + b2v)));
        atomicAdd(&g_diag[u], w * w);
        g_csr[base + i] = make_uint2(u, __float_as_uint(w));   // single ST.64
    }
    __syncthreads();
    if (k <= 1) return;
    int warp = t >> 5;
    int lane = t & 31;
    for (int a = warp; a < k; a += 8) {
        uint2 ea = g_csr[base + a];              // L1-hot broadcast load
        float wa = __uint_as_float(ea.y);
        unsigned ua = ea.x;
        for (int b = a + 1 + lane; b < k; b += 32) {
            uint2 eb = g_csr[base + b];          // L1-hot
            unsigned ub = eb.x;
            unsigned lo = min(ua, ub), hi = max(ua, ub);
            atomicAdd(&g_C[(lo << 11) + hi], wa * __uint_as_float(eb.y));
        }
    }
}

// ---------------- kernel 6: sym + scale + top-3 + scatter S (R8 winner) ----
__device__ __forceinline__ bool better(float v, int i, float bv, int bi) {
    return (v > bv) || (v == bv && (unsigned)i < (unsigned)bi);
}
__device__ __forceinline__ void ins3(float v, int i,
                                     float& v0, int& i0, float& v1, int& i1,
                                     float& v2, int& i2) {
    if (better(v, i, v0, i0)) { v2 = v1; i2 = i1; v1 = v0; i1 = i0; v0 = v; i0 = i; }
    else if (better(v, i, v1, i1)) { v2 = v1; i2 = i1; v1 = v; i1 = i; }
    else if (better(v, i, v2, i2)) { v2 = v; i2 = i; }
}

__global__ void k_topk(float* __restrict__ outS) {
    __shared__ float sDh[U_];            // 8 KB
    __shared__ float sB[32][9];          // transposed tile: sB[c_local][r_local]
    int tx = threadIdx.x, ty = threadIdx.y;     // (32,8)
    int tid = ty * 32 + tx;
    for (int i = tid; i < U_; i += 256) sDh[i] = g_Dh[i];
    __syncthreads();
    int r0 = blockIdx.x * 8;
    int d0 = (r0 >> 5) << 5;             // the 32-wide tile containing rows r0..r0+7
    int r = r0 + ty;
    float dhr = sDh[r];
    float dg = g_diag[r];
    float v0 = -1.0f, v1 = -1.0f, v2 = -1.0f;
    int   i0 = -1,    i1 = -1,    i2 = -1;
    int li = tid >> 3, lj = tid & 7;     // load coords for transposed tile
    for (int c0 = 0; c0 < U_; c0 += 32) {
        bool useT = (c0 <= d0);          // uniform across block
        bool useD = (c0 >= d0);
        if (useT) {
            __syncthreads();             // protect sB reuse across iterations
            sB[li][lj] = g_C[(size_t)(c0 + li) * U_ + (r0 + lj)];
            __syncthreads();
        }
        int c = c0 + tx;
        float val = 0.0f;
        if (useD) val += g_C[(size_t)r * U_ + c];   // upper triangle / diagonal
        if (useT) val += sB[tx][ty];                // C[c][r] (upper triangle)
        if (c == r) val += dg;
        float v = val * dhr * sDh[c];
        if (v > 0.0f) ins3(v, c, v0, i0, v1, i1, v2, i2);
    }
    #pragma unroll
    for (int off = 16; off > 0; off >>= 1) {
        float ov0 = __shfl_down_sync(0xffffffffu, v0, off);
        float ov1 = __shfl_down_sync(0xffffffffu, v1, off);
        float ov2 = __shfl_down_sync(0xffffffffu, v2, off);
        int   oi0 = __shfl_down_sync(0xffffffffu, i0, off);
        int   oi1 = __shfl_down_sync(0xffffffffu, i1, off);
        int   oi2 = __shfl_down_sync(0xffffffffu, i2, off);
        if (ov0 > 0.0f) ins3(ov0, oi0, v0, i0, v1, i1, v2, i2);
        if (ov1 > 0.0f) ins3(ov1, oi1, v0, i0, v1, i1, v2, i2);
        if (ov2 > 0.0f) ins3(ov2, oi2, v0, i0, v1, i1, v2, i2);
    }
    if (tx == 0) {
        float mv[3] = {v0, v1, v2};
        int   mi[3] = {i0, i1, i2};
        #pragma unroll
        for (int q = 0; q < 3; q++) {
            if (mv[q] > 0.0f) {
                float vh = 0.5f * mv[q];
                atomicAdd(&outS[(size_t)r * U_ + mi[q]], vh);
                atomicAdd(&outS[(size_t)mi[q] * U_ + r], vh);
            }
        }
    }
}

// ---------------------------------------------------------------------------
extern "C" void kernel_launch(void* const* d_in, const int* in_sizes, int n_in,
                              void* d_out, int out_size) {
    const float* x   = (const float*)d_in[0];
    const float* w1  = (const float*)d_in[1];
    const float* b1  = (const float*)d_in[2];
    const float* w2  = (const float*)d_in[3];
    const float* b2  = (const float*)d_in[4];
    const int*   src = (const int*)d_in[5];
    const int*   dst = (const int*)d_in[6];
    int E = in_sizes[5];
    if (E > EMAX) E = EMAX;

    float* outS = (float*)d_out;
    int write_du = (out_size >= U_ * U_ + U_) ? 1 : 0;

    k_zero_small<<<64, 256>>>();
    k_init<<<1024, 256>>>(outS, src, dst, E);
    k_findeg<<<I_ / 256, 256>>>(outS + (size_t)U_ * U_, write_du);
    k_proj<<<NN_ / 32, 256>>>(x, w1, b1);
    k_scatter<<<(E + 255) / 256, 256>>>(src, dst, E);
    k_wpairs<<<I_, 256>>>(w2, b2);
    k_topk<<<U_ / 8, dim3(32, 8)>>>(outS);
}